// round 14
// baseline (speedup 1.0000x reference)
#include <cuda_runtime.h>
#include <math.h>

// Problem constants (fixed by the dataset)
#define NN 100000
#define EE 1600000
#define NB_SCAN ((NN + 1023) / 1024)
#define NP 100096           // NN padded to 391*256 tiles

typedef unsigned long long u64;

// ---------------- device scratch (static: no allocation allowed) ----------------
__device__ int   g_ns[NN];
__device__ int   g_s[NN];
__device__ int   g_inc[NN];
__device__ int   g_bsums[256];
__device__ int   g_rowptr[NN + 1];
__device__ int   g_cursor[NN];
__device__ int4  g_epack[EE];     // per-edge {c, dl[c], dh[c], wB[c]} (floats as bits)
__device__ float4 g_nd[NN];       // (dl, dh, dll, dhh)
__device__ float4 g_nd2[NN];      // (dl, dh, wB_node, 0)   wB_node = cc? dll : -dhh
__device__ float g_xpad[(size_t)NP * 64];  // padded copy of x
__device__ float g_aggA[(size_t)NP * 128]; // [aggL | aggH]
__device__ float g_xab [(size_t)NP * 128]; // [xl   | xh  ]
__device__ float g_aggB[(size_t)NP * 128]; // [aggLL| aggHH]

// ---------------- f32x2 packed-FMA helpers ----------------
__device__ __forceinline__ u64 pk2(float v) {
    u64 r; asm("mov.b64 %0, {%1, %1};" : "=l"(r) : "f"(v)); return r;
}
__device__ __forceinline__ u64 pk(float lo, float hi) {
    u64 r; asm("mov.b64 %0, {%1, %2};" : "=l"(r) : "f"(lo), "f"(hi)); return r;
}
__device__ __forceinline__ void fma2(u64& d, u64 a, u64 b) {
    asm("fma.rn.f32x2 %0, %1, %2, %0;" : "+l"(d) : "l"(a), "l"(b));
}
__device__ __forceinline__ float2 up2(u64 v) {
    float2 f; asm("mov.b64 {%0, %1}, %2;" : "=f"(f.x), "=f"(f.y) : "l"(v)); return f;
}

// ---------------- prep: zero counters + copy x (one kernel) ----------------
__global__ void k_pre(const float* __restrict__ x) {
    int i = blockIdx.x * blockDim.x + threadIdx.x;   // one float4 each, exact grid
    ((float4*)g_xpad)[i] = ((const float4*)x)[i];
    if (i < NN) { g_ns[i] = 0; g_s[i] = 0; }
}

__global__ void k_count(const int* __restrict__ ei, const int* __restrict__ ccm) {
    int e = blockIdx.x * blockDim.x + threadIdx.x;
    if (e >= EE) return;
    int c = ei[e];       // edge_index[0] = col (source)
    int r = ei[EE + e];  // edge_index[1] = row (target)
    if (r != c) {
        atomicAdd(&g_ns[r], 1);
        if (ccm[c]) atomicAdd(&g_s[r], 1);
    }
}

__global__ void k_scan1() {
    __shared__ int sh[1024];
    int t = threadIdx.x;
    int i = blockIdx.x * 1024 + t;
    int v = (i < NN) ? g_ns[i] : 0;
    sh[t] = v;
    __syncthreads();
    for (int off = 1; off < 1024; off <<= 1) {
        int add = (t >= off) ? sh[t - off] : 0;
        __syncthreads();
        sh[t] += add;
        __syncthreads();
    }
    if (i < NN) g_inc[i] = sh[t];
    if (t == 1023) g_bsums[blockIdx.x] = sh[1023];
}

__global__ void k_scan2() {
    __shared__ int sh[128];
    int t = threadIdx.x;
    int v = (t < NB_SCAN) ? g_bsums[t] : 0;
    sh[t] = v;
    __syncthreads();
    for (int off = 1; off < 128; off <<= 1) {
        int add = (t >= off) ? sh[t - off] : 0;
        __syncthreads();
        sh[t] += add;
        __syncthreads();
    }
    if (t < NB_SCAN) g_bsums[t] = sh[t] - v;   // exclusive
    if (t == 0) g_rowptr[0] = 0;
}

__global__ void k_final_csr(const int* __restrict__ ccm) {
    int i = blockIdx.x * blockDim.x + threadIdx.x;
    if (i >= NN) return;
    int pref = g_bsums[i >> 10];
    int inc  = g_inc[i];
    int ns   = g_ns[i];
    int s    = g_s[i];
    g_rowptr[i + 1] = inc + pref;
    g_cursor[i]     = inc + pref - ns;   // == rowptr[i]
    int   cci = ccm[i];
    float cc = cci ? 1.0f : 0.0f;
    float4 nd;
    nd.x = rsqrtf(1.0f + cc * (float)ns);          // dl
    nd.y = rsqrtf(1.0f + (1.0f - cc) * (float)ns); // dh
    nd.z = rsqrtf(1.0f + (float)s);                // dll
    nd.w = rsqrtf(1.0f + (float)(ns - s));         // dhh
    g_nd[i] = nd;
    float4 n2;
    n2.x = nd.x; n2.y = nd.y;
    n2.z = cci ? nd.z : -nd.w;   // wB_node, sign encodes cc[c]
    n2.w = 0.f;
    g_nd2[i] = n2;
}

__global__ void k_scatter(const int* __restrict__ ei) {
    int e = blockIdx.x * blockDim.x + threadIdx.x;
    if (e >= EE) return;
    int c = ei[e];
    int r = ei[EE + e];
    if (r == c) return;
    int pos = atomicAdd(&g_cursor[r], 1);
    float4 n2 = g_nd2[c];
    int4 m;
    m.x = c;
    m.y = __float_as_int(n2.x);   // dl[c]
    m.z = __float_as_int(n2.y);   // dh[c]
    m.w = __float_as_int(n2.z);   // wB[c] (signed)
    g_epack[pos] = m;
}

// ---------------- SpMM stage A: one warp per row, shfl-distributed edges ----------------
__global__ void k_spmmA(const float* __restrict__ x, const int* __restrict__ ccm) {
    int r    = (blockIdx.x * blockDim.x + threadIdx.x) >> 5;
    int lane = threadIdx.x & 31;
    if (r >= NN) return;
    int e0 = g_rowptr[r], e1 = g_rowptr[r + 1];
    int ccr = ccm[r];
    float sx = 0.f, sy = 0.f;
    for (int base = e0; base < e1; base += 32) {
        int idx = base + lane;
        int4 m = (idx < e1) ? __ldg(&g_epack[idx]) : make_int4(0, 0, 0, 0);
        int   mc = m.x;
        float mw = __int_as_float(ccr ? m.y : m.z);  // warp-uniform select
        int n = min(32, e1 - base);
        int i = 0;
        for (; i + 4 <= n; i += 4) {
            int c0 = __shfl_sync(0xffffffffu, mc, i);
            int c1 = __shfl_sync(0xffffffffu, mc, i + 1);
            int c2 = __shfl_sync(0xffffffffu, mc, i + 2);
            int c3 = __shfl_sync(0xffffffffu, mc, i + 3);
            float w0 = __shfl_sync(0xffffffffu, mw, i);
            float w1 = __shfl_sync(0xffffffffu, mw, i + 1);
            float w2 = __shfl_sync(0xffffffffu, mw, i + 2);
            float w3 = __shfl_sync(0xffffffffu, mw, i + 3);
            float2 v0 = __ldg((const float2*)(x + (size_t)c0 * 64 + 2 * lane));
            float2 v1 = __ldg((const float2*)(x + (size_t)c1 * 64 + 2 * lane));
            float2 v2 = __ldg((const float2*)(x + (size_t)c2 * 64 + 2 * lane));
            float2 v3 = __ldg((const float2*)(x + (size_t)c3 * 64 + 2 * lane));
            sx += w0 * v0.x; sy += w0 * v0.y;
            sx += w1 * v1.x; sy += w1 * v1.y;
            sx += w2 * v2.x; sy += w2 * v2.y;
            sx += w3 * v3.x; sy += w3 * v3.y;
        }
        for (; i < n; i++) {
            int   c = __shfl_sync(0xffffffffu, mc, i);
            float w = __shfl_sync(0xffffffffu, mw, i);
            float2 v = __ldg((const float2*)(x + (size_t)c * 64 + 2 * lane));
            sx += w * v.x; sy += w * v.y;
        }
    }
    float2 xr = *(const float2*)(x + (size_t)r * 64 + 2 * lane);
    float4 nd = g_nd[r];
    float2 aL, aH;
    if (ccr) {
        float d = nd.x;
        aL.x = d * d * xr.x + d * sx; aL.y = d * d * xr.y + d * sy;
        aH = xr;  // dh = 1, no off-diag contribution
    } else {
        aL = xr;  // dl = 1
        float d = nd.y;
        aH.x = d * d * xr.x + d * sx; aH.y = d * d * xr.y + d * sy;
    }
    float* o = g_aggA + (size_t)r * 128;
    *(float2*)(o + 2 * lane)      = aL;
    *(float2*)(o + 64 + 2 * lane) = aH;
}

// ---------------- SpMM stage B: one warp per row, shfl-distributed edges ----------------
__global__ void k_spmmB() {
    int r    = (blockIdx.x * blockDim.x + threadIdx.x) >> 5;
    int lane = threadIdx.x & 31;
    if (r >= NN) return;
    int e0 = g_rowptr[r], e1 = g_rowptr[r + 1];
    float slx = 0.f, sly = 0.f, shx = 0.f, shy = 0.f;
    for (int base = e0; base < e1; base += 32) {
        int idx = base + lane;
        int4 m = (idx < e1) ? __ldg(&g_epack[idx]) : make_int4(0, 0, 0, 0);
        int   mc = m.x;
        float mw = __int_as_float(m.w);   // wB, sign selects branch
        int n = min(32, e1 - base);
        int i = 0;
        for (; i + 4 <= n; i += 4) {
            int c0 = __shfl_sync(0xffffffffu, mc, i);
            int c1 = __shfl_sync(0xffffffffu, mc, i + 1);
            int c2 = __shfl_sync(0xffffffffu, mc, i + 2);
            int c3 = __shfl_sync(0xffffffffu, mc, i + 3);
            float w0 = __shfl_sync(0xffffffffu, mw, i);
            float w1 = __shfl_sync(0xffffffffu, mw, i + 1);
            float w2 = __shfl_sync(0xffffffffu, mw, i + 2);
            float w3 = __shfl_sync(0xffffffffu, mw, i + 3);
            const float* p0 = g_xab + (size_t)c0 * 128 + (w0 > 0.f ? 0 : 64) + 2 * lane;
            const float* p1 = g_xab + (size_t)c1 * 128 + (w1 > 0.f ? 0 : 64) + 2 * lane;
            const float* p2 = g_xab + (size_t)c2 * 128 + (w2 > 0.f ? 0 : 64) + 2 * lane;
            const float* p3 = g_xab + (size_t)c3 * 128 + (w3 > 0.f ? 0 : 64) + 2 * lane;
            float2 v0 = __ldg((const float2*)p0);
            float2 v1 = __ldg((const float2*)p1);
            float2 v2 = __ldg((const float2*)p2);
            float2 v3 = __ldg((const float2*)p3);
            if (w0 > 0.f) { slx += w0 * v0.x; sly += w0 * v0.y; } else { shx -= w0 * v0.x; shy -= w0 * v0.y; }
            if (w1 > 0.f) { slx += w1 * v1.x; sly += w1 * v1.y; } else { shx -= w1 * v1.x; shy -= w1 * v1.y; }
            if (w2 > 0.f) { slx += w2 * v2.x; sly += w2 * v2.y; } else { shx -= w2 * v2.x; shy -= w2 * v2.y; }
            if (w3 > 0.f) { slx += w3 * v3.x; sly += w3 * v3.y; } else { shx -= w3 * v3.x; shy -= w3 * v3.y; }
        }
        for (; i < n; i++) {
            int   c = __shfl_sync(0xffffffffu, mc, i);
            float w = __shfl_sync(0xffffffffu, mw, i);
            const float* p = g_xab + (size_t)c * 128 + (w > 0.f ? 0 : 64) + 2 * lane;
            float2 v = __ldg((const float2*)p);
            if (w > 0.f) { slx += w * v.x; sly += w * v.y; }
            else         { shx -= w * v.x; shy -= w * v.y; }
        }
    }
    float4 nd = g_nd[r];
    float2 xl = *(const float2*)(g_xab + (size_t)r * 128 + 2 * lane);
    float2 xh = *(const float2*)(g_xab + (size_t)r * 128 + 64 + 2 * lane);
    float dll = nd.z, dhh = nd.w;
    float* o = g_aggB + (size_t)r * 128;
    float2 aL, aH;
    aL.x = dll * dll * xl.x + dll * slx;  aL.y = dll * dll * xl.y + dll * sly;
    aH.x = dhh * dhh * xh.x + dhh * shx;  aH.y = dhh * dhh * xh.y + dhh * shy;
    *(float2*)(o + 2 * lane)      = aL;
    *(float2*)(o + 64 + 2 * lane) = aH;
}

// ---------------- tiled dense GEMM (8 rows x 8 cols per thread, contiguous rows) ----------------
__device__ __forceinline__ void load_w64(float* sW, const float* __restrict__ W, int t) {
    const float4* src = (const float4*)W;
    float4* dst = (float4*)sW;
#pragma unroll
    for (int i = 0; i < 4; i++) dst[t + i * 256] = src[t + i * 256];
}

__device__ __forceinline__ void load_w64s(float* sW, const float* __restrict__ W, int t, float s) {
    const float4* src = (const float4*)W;
    float4* dst = (float4*)sW;
#pragma unroll
    for (int i = 0; i < 4; i++) {
        float4 v = src[t + i * 256];
        v.x *= s; v.y *= s; v.z *= s; v.w *= s;
        dst[t + i * 256] = v;
    }
}

template<int ASTRIDE>
__device__ __forceinline__ void tacc(u64 acc[8][4], const float* __restrict__ Abase,
                                     const float* sW, int tx, float scale) {
#pragma unroll 2
    for (int k0 = 0; k0 < 64; k0 += 4) {
        float4 a[8];
#pragma unroll
        for (int r = 0; r < 8; r++)
            a[r] = __ldg((const float4*)(Abase + (size_t)r * 32 * ASTRIDE + k0));
#pragma unroll
        for (int kk = 0; kk < 4; kk++) {
            const ulonglong2* wp = (const ulonglong2*)(sW + (k0 + kk) * 64 + tx * 8);
            ulonglong2 w0 = wp[0];
            ulonglong2 w1 = wp[1];
#pragma unroll
            for (int r = 0; r < 8; r++) {
                float av = ((kk == 0) ? a[r].x : (kk == 1) ? a[r].y : (kk == 2) ? a[r].z : a[r].w) * scale;
                u64 aa = pk2(av);
                fma2(acc[r][0], aa, w0.x); fma2(acc[r][1], aa, w0.y);
                fma2(acc[r][2], aa, w1.x); fma2(acc[r][3], aa, w1.y);
            }
        }
    }
}

template<int ASTRIDE>
__device__ __forceinline__ void tacc_s(u64 acc[8][4], const float* __restrict__ Abase,
                                       const float* sW, int tx, const float s[8]) {
#pragma unroll 2
    for (int k0 = 0; k0 < 64; k0 += 4) {
        float4 a[8];
#pragma unroll
        for (int r = 0; r < 8; r++)
            a[r] = __ldg((const float4*)(Abase + (size_t)r * 32 * ASTRIDE + k0));
#pragma unroll
        for (int kk = 0; kk < 4; kk++) {
            const ulonglong2* wp = (const ulonglong2*)(sW + (k0 + kk) * 64 + tx * 8);
            ulonglong2 w0 = wp[0];
            ulonglong2 w1 = wp[1];
#pragma unroll
            for (int r = 0; r < 8; r++) {
                float av = ((kk == 0) ? a[r].x : (kk == 1) ? a[r].y : (kk == 2) ? a[r].z : a[r].w) * s[r];
                u64 aa = pk2(av);
                fma2(acc[r][0], aa, w0.x); fma2(acc[r][1], aa, w0.y);
                fma2(acc[r][2], aa, w1.x); fma2(acc[r][3], aa, w1.y);
            }
        }
    }
}

__device__ __forceinline__ void acc_zero8(u64 acc[8][4]) {
#pragma unroll
    for (int r = 0; r < 8; r++)
#pragma unroll
        for (int j = 0; j < 4; j++) acc[r][j] = 0ull;
}

template<int OSTRIDE>
__device__ __forceinline__ void store_relu8(float* Obase, int row0, const u64 acc[8][4]) {
#pragma unroll
    for (int r = 0; r < 8; r++) {
        int row = row0 + 32 * r;
        if (row < NN) {
            float2 a = up2(acc[r][0]);
            float2 b = up2(acc[r][1]);
            float2 c = up2(acc[r][2]);
            float2 d = up2(acc[r][3]);
            float4 v0, v1;
            v0.x = fmaxf(a.x, 0.f); v0.y = fmaxf(a.y, 0.f);
            v0.z = fmaxf(b.x, 0.f); v0.w = fmaxf(b.y, 0.f);
            v1.x = fmaxf(c.x, 0.f); v1.y = fmaxf(c.y, 0.f);
            v1.z = fmaxf(d.x, 0.f); v1.w = fmaxf(d.y, 0.f);
            float4* o = (float4*)(Obase + (size_t)r * 32 * OSTRIDE);
            o[0] = v0; o[1] = v1;
        }
    }
}

// XL = relu(aggL@W1l + x@W1r), XH = relu(aggH@W3l + x@W3r), packed into g_xab
__global__ __launch_bounds__(256) void k_gemmA(const float* __restrict__ W1l,
                                               const float* __restrict__ W1r,
                                               const float* __restrict__ W3l,
                                               const float* __restrict__ W3r) {
    __shared__ float sW[4096];
    int t = threadIdx.x;
    int tx = t & 7, ty = t >> 3;
    int row0 = blockIdx.x * 256 + ty;
    const float* aggL = g_aggA + (size_t)row0 * 128;
    const float* aggH = aggL + 64;
    const float* xr   = g_xpad + (size_t)row0 * 64;
    u64 acc[8][4];

    load_w64(sW, W1l, t); __syncthreads();
    acc_zero8(acc);
    tacc<128>(acc, aggL, sW, tx, 1.0f);
    __syncthreads(); load_w64(sW, W1r, t); __syncthreads();
    tacc<64>(acc, xr, sW, tx, 1.0f);
    store_relu8<128>(g_xab + (size_t)row0 * 128 + tx * 8, row0, acc);
    __syncthreads();

    load_w64(sW, W3l, t); __syncthreads();
    acc_zero8(acc);
    tacc<128>(acc, aggH, sW, tx, 1.0f);
    __syncthreads(); load_w64(sW, W3r, t); __syncthreads();
    tacc<64>(acc, xr, sW, tx, 1.0f);
    store_relu8<128>(g_xab + (size_t)row0 * 128 + 64 + tx * 8, row0, acc);
}

// ---------------- stage-2 dense + final linear fused ----------------
// t1 = relu( lamx*(x@WX) + laml*(aggLL@W2l + xl@W2r) + lamh*(aggHH@W4l + xh@W4r) )
// out = t1 @ lin_W + lin_b  (staged through smem, no global t1)
__global__ __launch_bounds__(256) void k_gemm3out(const int* __restrict__ ccm,
                                                  const float* __restrict__ W2l,
                                                  const float* __restrict__ W2r,
                                                  const float* __restrict__ W4l,
                                                  const float* __restrict__ W4r,
                                                  const float* __restrict__ WX,
                                                  const float* __restrict__ lam1,
                                                  const float* __restrict__ lam2,
                                                  const float* __restrict__ linW,
                                                  const float* __restrict__ linb,
                                                  float* __restrict__ out) {
    __shared__ float sW[4096];
    __shared__ float sLW[2560];        // linW 64x40
    __shared__ float sB[40];
    __shared__ float sT[64 * 65];      // t1 staging chunk, stride 65 (conflict-free)
    int t = threadIdx.x;
    int tx = t & 7, ty = t >> 3;
    int row0 = blockIdx.x * 256 + ty;

    float a0 = __ldg(&lam1[0]), a1 = __ldg(&lam1[1]);
    float m1 = fmaxf(a0, a1);
    float e0 = expf(a0 - m1), e1 = expf(a1 - m1);
    float inv1 = 1.0f / (e0 + e1);
    float lamxl = e0 * inv1, laml = e1 * inv1;
    float b0 = __ldg(&lam2[0]), b1 = __ldg(&lam2[1]);
    float m2 = fmaxf(b0, b1);
    float f0 = expf(b0 - m2), f1 = expf(b1 - m2);
    float inv2 = 1.0f / (f0 + f1);
    float lamxh = f0 * inv2, lamh = f1 * inv2;

    float s[8];
#pragma unroll
    for (int r = 0; r < 8; r++) {
        int row = row0 + 32 * r;
        int rr = row < NN ? row : NN - 1;
        s[r] = ccm[rr] ? lamxl : lamxh;
    }

    const float* xr    = g_xpad + (size_t)row0 * 64;
    const float* aggLL = g_aggB + (size_t)row0 * 128;
    const float* aggHH = aggLL + 64;
    const float* xlr   = g_xab + (size_t)row0 * 128;
    const float* xhr   = xlr + 64;

    u64 acc[8][4];
    acc_zero8(acc);

    load_w64(sW, WX, t);
    {   // load linW + bias alongside first weight load
        const float4* src = (const float4*)linW;
        float4* dst = (float4*)sLW;
#pragma unroll
        for (int i = 0; i < 3; i++) {
            int idx = t + i * 256;
            if (idx < 640) dst[idx] = src[idx];
        }
        if (t < 40) sB[t] = linb[t];
    }
    __syncthreads();
    tacc_s<64>(acc, xr, sW, tx, s);
    __syncthreads(); load_w64s(sW, W2l, t, laml); __syncthreads();
    tacc<128>(acc, aggLL, sW, tx, 1.0f);
    __syncthreads(); load_w64s(sW, W2r, t, laml); __syncthreads();
    tacc<128>(acc, xlr, sW, tx, 1.0f);
    __syncthreads(); load_w64s(sW, W4l, t, lamh); __syncthreads();
    tacc<128>(acc, aggHH, sW, tx, 1.0f);
    __syncthreads(); load_w64s(sW, W4r, t, lamh); __syncthreads();
    tacc<128>(acc, xhr, sW, tx, 1.0f);

    // 4 chunks of 64 rows: stage relu(t1) to smem, then apply lin layer
#pragma unroll 1
    for (int ck = 0; ck < 4; ck++) {
        __syncthreads();
#pragma unroll
        for (int rr = 0; rr < 2; rr++) {
            int r = 2 * ck + rr;
            float* dT = sT + (rr * 32 + ty) * 65 + tx * 8;
            float2 a = up2(acc[r][0]);
            float2 b = up2(acc[r][1]);
            float2 c = up2(acc[r][2]);
            float2 d = up2(acc[r][3]);
            dT[0] = fmaxf(a.x, 0.f); dT[1] = fmaxf(a.y, 0.f);
            dT[2] = fmaxf(b.x, 0.f); dT[3] = fmaxf(b.y, 0.f);
            dT[4] = fmaxf(c.x, 0.f); dT[5] = fmaxf(c.y, 0.f);
            dT[6] = fmaxf(d.x, 0.f); dT[7] = fmaxf(d.y, 0.f);
        }
        __syncthreads();
        int lrow = t >> 2;
        int seg  = (t & 3) * 10;
        int grow = blockIdx.x * 256 + ck * 64 + lrow;
        u64 acc5[5];
#pragma unroll
        for (int j = 0; j < 5; j++) acc5[j] = pk(sB[seg + 2 * j], sB[seg + 2 * j + 1]);
        const float* Tr = sT + lrow * 65;
#pragma unroll 4
        for (int k = 0; k < 64; k++) {
            u64 aa = pk2(Tr[k]);
            const u64* wr = (const u64*)(sLW + k * 40 + seg);
#pragma unroll
            for (int j = 0; j < 5; j++) fma2(acc5[j], aa, wr[j]);
        }
        if (grow < NN) {
            float* o = out + (size_t)grow * 40 + seg;
#pragma unroll
            for (int j = 0; j < 5; j++) {
                float2 v = up2(acc5[j]);
                *(float2*)(o + 2 * j) = v;
            }
        }
    }
}

// ---------------- launch ----------------
extern "C" void kernel_launch(void* const* d_in, const int* in_sizes, int n_in,
                              void* d_out, int out_size) {
    (void)in_sizes; (void)n_in; (void)out_size;
    const float* x    = (const float*)d_in[0];
    const int*   ei   = (const int*)d_in[1];
    const int*   ccm  = (const int*)d_in[2];
    const float* W1l  = (const float*)d_in[3];
    const float* W1r  = (const float*)d_in[4];
    const float* W2l  = (const float*)d_in[5];
    const float* W2r  = (const float*)d_in[6];
    const float* W3l  = (const float*)d_in[7];
    const float* W3r  = (const float*)d_in[8];
    const float* W4l  = (const float*)d_in[9];
    const float* W4r  = (const float*)d_in[10];
    const float* WX   = (const float*)d_in[11];
    const float* lam1 = (const float*)d_in[12];
    const float* lam2 = (const float*)d_in[13];
    const float* linW = (const float*)d_in[14];
    const float* linb = (const float*)d_in[15];
    float* out = (float*)d_out;

    const int GB = (NP / 256);   // 391 tiled blocks

    k_pre      <<<NN * 16 / 256, 256>>>(x);            // 6250 blocks, exact
    k_count    <<<(EE + 255) / 256, 256>>>(ei, ccm);
    k_scan1    <<<NB_SCAN, 1024>>>();
    k_scan2    <<<1, 128>>>();
    k_final_csr<<<(NN + 255) / 256, 256>>>(ccm);
    k_scatter  <<<(EE + 255) / 256, 256>>>(ei);
    k_spmmA    <<<(NN * 32 + 255) / 256, 256>>>(x, ccm);
    k_gemmA    <<<GB, 256>>>(W1l, W1r, W3l, W3r);
    k_spmmB    <<<(NN * 32 + 255) / 256, 256>>>();
    k_gemm3out <<<GB, 256>>>(ccm, W2l, W2r, W4l, W4r, WX, lam1, lam2, linW, linb, out);
}

// round 17
// speedup vs baseline: 1.1686x; 1.1686x over previous
#include <cuda_runtime.h>
#include <math.h>

// Problem constants (fixed by the dataset)
#define NN 100000
#define EE 1600000
#define NB_SCAN ((NN + 1023) / 1024)
#define NP 100096           // NN padded to 391*256 tiles

typedef unsigned long long u64;

// ---------------- device scratch (static: no allocation allowed) ----------------
__device__ int   g_cnt[NN];       // packed: low 16 = ns, high 16 = s
__device__ int   g_inc[NN];
__device__ int   g_bsums[256];
__device__ int   g_rowptr[NN + 1];
__device__ int   g_cursor[NN];
__device__ int4  g_epack[EE];     // per-edge {c, dl[c], dh[c], wB[c]} (floats as bits)
__device__ float4 g_nd[NN];       // (dl, dh, dll, dhh)
__device__ float4 g_nd2[NN];      // (dl, dh, wB_node, 0)   wB_node = cc? dll : -dhh
__device__ float g_xpad[(size_t)NP * 64];  // padded copy of x
__device__ float g_aggA[(size_t)NP * 128]; // [aggL | aggH]
__device__ float g_xab [(size_t)NP * 128]; // [xl   | xh  ]
__device__ float g_aggB[(size_t)NP * 128]; // [aggLL| aggHH]
__device__ float g_t1  [(size_t)NP * 64];

// ---------------- f32x2 packed-FMA helpers ----------------
__device__ __forceinline__ u64 pk2(float v) {
    u64 r; asm("mov.b64 %0, {%1, %1};" : "=l"(r) : "f"(v)); return r;
}
__device__ __forceinline__ u64 pk(float lo, float hi) {
    u64 r; asm("mov.b64 %0, {%1, %2};" : "=l"(r) : "f"(lo), "f"(hi)); return r;
}
__device__ __forceinline__ void fma2(u64& d, u64 a, u64 b) {
    asm("fma.rn.f32x2 %0, %1, %2, %0;" : "+l"(d) : "l"(a), "l"(b));
}
__device__ __forceinline__ float2 up2(u64 v) {
    float2 f; asm("mov.b64 {%0, %1}, %2;" : "=f"(f.x), "=f"(f.y) : "l"(v)); return f;
}

// ---------------- prep: zero counters + copy x (one kernel) ----------------
__global__ void k_pre(const float* __restrict__ x) {
    int i = blockIdx.x * blockDim.x + threadIdx.x;   // one float4 each, exact grid
    ((float4*)g_xpad)[i] = ((const float4*)x)[i];
    if (i < NN) g_cnt[i] = 0;
}

__global__ void k_count(const int* __restrict__ ei, const int* __restrict__ ccm) {
    int e = blockIdx.x * blockDim.x + threadIdx.x;
    if (e >= EE) return;
    int c = ei[e];       // edge_index[0] = col (source)
    int r = ei[EE + e];  // edge_index[1] = row (target)
    if (r != c) {
        int add = 1 + (ccm[c] ? 0x10000 : 0);
        atomicAdd(&g_cnt[r], add);
    }
}

__global__ void k_scan1() {
    __shared__ int sh[1024];
    int t = threadIdx.x;
    int i = blockIdx.x * 1024 + t;
    int v = (i < NN) ? (g_cnt[i] & 0xffff) : 0;
    sh[t] = v;
    __syncthreads();
    for (int off = 1; off < 1024; off <<= 1) {
        int add = (t >= off) ? sh[t - off] : 0;
        __syncthreads();
        sh[t] += add;
        __syncthreads();
    }
    if (i < NN) g_inc[i] = sh[t];
    if (t == 1023) g_bsums[blockIdx.x] = sh[1023];
}

__global__ void k_scan2() {
    __shared__ int sh[128];
    int t = threadIdx.x;
    int v = (t < NB_SCAN) ? g_bsums[t] : 0;
    sh[t] = v;
    __syncthreads();
    for (int off = 1; off < 128; off <<= 1) {
        int add = (t >= off) ? sh[t - off] : 0;
        __syncthreads();
        sh[t] += add;
        __syncthreads();
    }
    if (t < NB_SCAN) g_bsums[t] = sh[t] - v;   // exclusive
    if (t == 0) g_rowptr[0] = 0;
}

__global__ void k_final_csr(const int* __restrict__ ccm) {
    int i = blockIdx.x * blockDim.x + threadIdx.x;
    if (i >= NN) return;
    int pref = g_bsums[i >> 10];
    int inc  = g_inc[i];
    int pk_  = g_cnt[i];
    int ns   = pk_ & 0xffff;
    int s    = pk_ >> 16;
    g_rowptr[i + 1] = inc + pref;
    g_cursor[i]     = inc + pref - ns;   // == rowptr[i]
    int   cci = ccm[i];
    float cc = cci ? 1.0f : 0.0f;
    float4 nd;
    nd.x = rsqrtf(1.0f + cc * (float)ns);          // dl
    nd.y = rsqrtf(1.0f + (1.0f - cc) * (float)ns); // dh
    nd.z = rsqrtf(1.0f + (float)s);                // dll
    nd.w = rsqrtf(1.0f + (float)(ns - s));         // dhh
    g_nd[i] = nd;
    float4 n2;
    n2.x = nd.x; n2.y = nd.y;
    n2.z = cci ? nd.z : -nd.w;   // wB_node, sign encodes cc[c]
    n2.w = 0.f;
    g_nd2[i] = n2;
}

__global__ void k_scatter(const int* __restrict__ ei) {
    int e = blockIdx.x * blockDim.x + threadIdx.x;
    if (e >= EE) return;
    int c = ei[e];
    int r = ei[EE + e];
    if (r == c) return;
    int pos = atomicAdd(&g_cursor[r], 1);
    float4 n2 = g_nd2[c];
    int4 m;
    m.x = c;
    m.y = __float_as_int(n2.x);   // dl[c]
    m.z = __float_as_int(n2.y);   // dh[c]
    m.w = __float_as_int(n2.z);   // wB[c] (signed)
    g_epack[pos] = m;
}

// ---------------- SpMM stage A: one warp per row, shfl-distributed edges ----------------
__global__ void k_spmmA(const float* __restrict__ x, const int* __restrict__ ccm) {
    int r    = (blockIdx.x * blockDim.x + threadIdx.x) >> 5;
    int lane = threadIdx.x & 31;
    if (r >= NN) return;
    int e0 = g_rowptr[r], e1 = g_rowptr[r + 1];
    int ccr = ccm[r];
    float sx = 0.f, sy = 0.f;
    for (int base = e0; base < e1; base += 32) {
        int idx = base + lane;
        int4 m = (idx < e1) ? __ldg(&g_epack[idx]) : make_int4(0, 0, 0, 0);
        int   mc = m.x;
        float mw = __int_as_float(ccr ? m.y : m.z);  // warp-uniform select
        int n = min(32, e1 - base);
        int i = 0;
        for (; i + 4 <= n; i += 4) {
            int c0 = __shfl_sync(0xffffffffu, mc, i);
            int c1 = __shfl_sync(0xffffffffu, mc, i + 1);
            int c2 = __shfl_sync(0xffffffffu, mc, i + 2);
            int c3 = __shfl_sync(0xffffffffu, mc, i + 3);
            float w0 = __shfl_sync(0xffffffffu, mw, i);
            float w1 = __shfl_sync(0xffffffffu, mw, i + 1);
            float w2 = __shfl_sync(0xffffffffu, mw, i + 2);
            float w3 = __shfl_sync(0xffffffffu, mw, i + 3);
            float2 v0 = __ldg((const float2*)(x + (size_t)c0 * 64 + 2 * lane));
            float2 v1 = __ldg((const float2*)(x + (size_t)c1 * 64 + 2 * lane));
            float2 v2 = __ldg((const float2*)(x + (size_t)c2 * 64 + 2 * lane));
            float2 v3 = __ldg((const float2*)(x + (size_t)c3 * 64 + 2 * lane));
            sx += w0 * v0.x; sy += w0 * v0.y;
            sx += w1 * v1.x; sy += w1 * v1.y;
            sx += w2 * v2.x; sy += w2 * v2.y;
            sx += w3 * v3.x; sy += w3 * v3.y;
        }
        for (; i < n; i++) {
            int   c = __shfl_sync(0xffffffffu, mc, i);
            float w = __shfl_sync(0xffffffffu, mw, i);
            float2 v = __ldg((const float2*)(x + (size_t)c * 64 + 2 * lane));
            sx += w * v.x; sy += w * v.y;
        }
    }
    float2 xr = *(const float2*)(x + (size_t)r * 64 + 2 * lane);
    float4 nd = g_nd[r];
    float2 aL, aH;
    if (ccr) {
        float d = nd.x;
        aL.x = d * d * xr.x + d * sx; aL.y = d * d * xr.y + d * sy;
        aH = xr;  // dh = 1, no off-diag contribution
    } else {
        aL = xr;  // dl = 1
        float d = nd.y;
        aH.x = d * d * xr.x + d * sx; aH.y = d * d * xr.y + d * sy;
    }
    float* o = g_aggA + (size_t)r * 128;
    *(float2*)(o + 2 * lane)      = aL;
    *(float2*)(o + 64 + 2 * lane) = aH;
}

// ---------------- SpMM stage B: one warp per row, shfl-distributed edges ----------------
__global__ void k_spmmB() {
    int r    = (blockIdx.x * blockDim.x + threadIdx.x) >> 5;
    int lane = threadIdx.x & 31;
    if (r >= NN) return;
    int e0 = g_rowptr[r], e1 = g_rowptr[r + 1];
    float slx = 0.f, sly = 0.f, shx = 0.f, shy = 0.f;
    for (int base = e0; base < e1; base += 32) {
        int idx = base + lane;
        int4 m = (idx < e1) ? __ldg(&g_epack[idx]) : make_int4(0, 0, 0, 0);
        int   mc = m.x;
        float mw = __int_as_float(m.w);   // wB, sign selects branch
        int n = min(32, e1 - base);
        int i = 0;
        for (; i + 4 <= n; i += 4) {
            int c0 = __shfl_sync(0xffffffffu, mc, i);
            int c1 = __shfl_sync(0xffffffffu, mc, i + 1);
            int c2 = __shfl_sync(0xffffffffu, mc, i + 2);
            int c3 = __shfl_sync(0xffffffffu, mc, i + 3);
            float w0 = __shfl_sync(0xffffffffu, mw, i);
            float w1 = __shfl_sync(0xffffffffu, mw, i + 1);
            float w2 = __shfl_sync(0xffffffffu, mw, i + 2);
            float w3 = __shfl_sync(0xffffffffu, mw, i + 3);
            const float* p0 = g_xab + (size_t)c0 * 128 + (w0 > 0.f ? 0 : 64) + 2 * lane;
            const float* p1 = g_xab + (size_t)c1 * 128 + (w1 > 0.f ? 0 : 64) + 2 * lane;
            const float* p2 = g_xab + (size_t)c2 * 128 + (w2 > 0.f ? 0 : 64) + 2 * lane;
            const float* p3 = g_xab + (size_t)c3 * 128 + (w3 > 0.f ? 0 : 64) + 2 * lane;
            float2 v0 = __ldg((const float2*)p0);
            float2 v1 = __ldg((const float2*)p1);
            float2 v2 = __ldg((const float2*)p2);
            float2 v3 = __ldg((const float2*)p3);
            if (w0 > 0.f) { slx += w0 * v0.x; sly += w0 * v0.y; } else { shx -= w0 * v0.x; shy -= w0 * v0.y; }
            if (w1 > 0.f) { slx += w1 * v1.x; sly += w1 * v1.y; } else { shx -= w1 * v1.x; shy -= w1 * v1.y; }
            if (w2 > 0.f) { slx += w2 * v2.x; sly += w2 * v2.y; } else { shx -= w2 * v2.x; shy -= w2 * v2.y; }
            if (w3 > 0.f) { slx += w3 * v3.x; sly += w3 * v3.y; } else { shx -= w3 * v3.x; shy -= w3 * v3.y; }
        }
        for (; i < n; i++) {
            int   c = __shfl_sync(0xffffffffu, mc, i);
            float w = __shfl_sync(0xffffffffu, mw, i);
            const float* p = g_xab + (size_t)c * 128 + (w > 0.f ? 0 : 64) + 2 * lane;
            float2 v = __ldg((const float2*)p);
            if (w > 0.f) { slx += w * v.x; sly += w * v.y; }
            else         { shx -= w * v.x; shy -= w * v.y; }
        }
    }
    float4 nd = g_nd[r];
    float2 xl = *(const float2*)(g_xab + (size_t)r * 128 + 2 * lane);
    float2 xh = *(const float2*)(g_xab + (size_t)r * 128 + 64 + 2 * lane);
    float dll = nd.z, dhh = nd.w;
    float* o = g_aggB + (size_t)r * 128;
    float2 aL, aH;
    aL.x = dll * dll * xl.x + dll * slx;  aL.y = dll * dll * xl.y + dll * sly;
    aH.x = dhh * dhh * xh.x + dhh * shx;  aH.y = dhh * dhh * xh.y + dhh * shy;
    *(float2*)(o + 2 * lane)      = aL;
    *(float2*)(o + 64 + 2 * lane) = aH;
}

// ---------------- tiled dense GEMM (8 rows x 8 cols per thread, contiguous rows) ----------------
__device__ __forceinline__ void load_w64(float* sW, const float* __restrict__ W, int t) {
    const float4* src = (const float4*)W;
    float4* dst = (float4*)sW;
#pragma unroll
    for (int i = 0; i < 4; i++) dst[t + i * 256] = src[t + i * 256];
}

__device__ __forceinline__ void load_w64s(float* sW, const float* __restrict__ W, int t, float s) {
    const float4* src = (const float4*)W;
    float4* dst = (float4*)sW;
#pragma unroll
    for (int i = 0; i < 4; i++) {
        float4 v = src[t + i * 256];
        v.x *= s; v.y *= s; v.z *= s; v.w *= s;
        dst[t + i * 256] = v;
    }
}

template<int ASTRIDE>
__device__ __forceinline__ void tacc(u64 acc[8][4], const float* __restrict__ Abase,
                                     const float* sW, int tx, float scale) {
#pragma unroll 2
    for (int k0 = 0; k0 < 64; k0 += 4) {
        float4 a[8];
#pragma unroll
        for (int r = 0; r < 8; r++)
            a[r] = __ldg((const float4*)(Abase + (size_t)r * 32 * ASTRIDE + k0));
#pragma unroll
        for (int kk = 0; kk < 4; kk++) {
            const ulonglong2* wp = (const ulonglong2*)(sW + (k0 + kk) * 64 + tx * 8);
            ulonglong2 w0 = wp[0];
            ulonglong2 w1 = wp[1];
#pragma unroll
            for (int r = 0; r < 8; r++) {
                float av = ((kk == 0) ? a[r].x : (kk == 1) ? a[r].y : (kk == 2) ? a[r].z : a[r].w) * scale;
                u64 aa = pk2(av);
                fma2(acc[r][0], aa, w0.x); fma2(acc[r][1], aa, w0.y);
                fma2(acc[r][2], aa, w1.x); fma2(acc[r][3], aa, w1.y);
            }
        }
    }
}

template<int ASTRIDE>
__device__ __forceinline__ void tacc_s(u64 acc[8][4], const float* __restrict__ Abase,
                                       const float* sW, int tx, const float s[8]) {
#pragma unroll 2
    for (int k0 = 0; k0 < 64; k0 += 4) {
        float4 a[8];
#pragma unroll
        for (int r = 0; r < 8; r++)
            a[r] = __ldg((const float4*)(Abase + (size_t)r * 32 * ASTRIDE + k0));
#pragma unroll
        for (int kk = 0; kk < 4; kk++) {
            const ulonglong2* wp = (const ulonglong2*)(sW + (k0 + kk) * 64 + tx * 8);
            ulonglong2 w0 = wp[0];
            ulonglong2 w1 = wp[1];
#pragma unroll
            for (int r = 0; r < 8; r++) {
                float av = ((kk == 0) ? a[r].x : (kk == 1) ? a[r].y : (kk == 2) ? a[r].z : a[r].w) * s[r];
                u64 aa = pk2(av);
                fma2(acc[r][0], aa, w0.x); fma2(acc[r][1], aa, w0.y);
                fma2(acc[r][2], aa, w1.x); fma2(acc[r][3], aa, w1.y);
            }
        }
    }
}

__device__ __forceinline__ void acc_zero8(u64 acc[8][4]) {
#pragma unroll
    for (int r = 0; r < 8; r++)
#pragma unroll
        for (int j = 0; j < 4; j++) acc[r][j] = 0ull;
}

template<int OSTRIDE>
__device__ __forceinline__ void store_relu8(float* Obase, int row0, const u64 acc[8][4]) {
#pragma unroll
    for (int r = 0; r < 8; r++) {
        int row = row0 + 32 * r;
        if (row < NN) {
            float2 a = up2(acc[r][0]);
            float2 b = up2(acc[r][1]);
            float2 c = up2(acc[r][2]);
            float2 d = up2(acc[r][3]);
            float4 v0, v1;
            v0.x = fmaxf(a.x, 0.f); v0.y = fmaxf(a.y, 0.f);
            v0.z = fmaxf(b.x, 0.f); v0.w = fmaxf(b.y, 0.f);
            v1.x = fmaxf(c.x, 0.f); v1.y = fmaxf(c.y, 0.f);
            v1.z = fmaxf(d.x, 0.f); v1.w = fmaxf(d.y, 0.f);
            float4* o = (float4*)(Obase + (size_t)r * 32 * OSTRIDE);
            o[0] = v0; o[1] = v1;
        }
    }
}

// XL = relu(aggL@W1l + x@W1r), XH = relu(aggH@W3l + x@W3r), packed into g_xab
__global__ __launch_bounds__(256) void k_gemmA(const float* __restrict__ W1l,
                                               const float* __restrict__ W1r,
                                               const float* __restrict__ W3l,
                                               const float* __restrict__ W3r) {
    __shared__ float sW[4096];
    int t = threadIdx.x;
    int tx = t & 7, ty = t >> 3;
    int row0 = blockIdx.x * 256 + ty;
    const float* aggL = g_aggA + (size_t)row0 * 128;
    const float* aggH = aggL + 64;
    const float* xr   = g_xpad + (size_t)row0 * 64;
    u64 acc[8][4];

    load_w64(sW, W1l, t); __syncthreads();
    acc_zero8(acc);
    tacc<128>(acc, aggL, sW, tx, 1.0f);
    __syncthreads(); load_w64(sW, W1r, t); __syncthreads();
    tacc<64>(acc, xr, sW, tx, 1.0f);
    store_relu8<128>(g_xab + (size_t)row0 * 128 + tx * 8, row0, acc);
    __syncthreads();

    load_w64(sW, W3l, t); __syncthreads();
    acc_zero8(acc);
    tacc<128>(acc, aggH, sW, tx, 1.0f);
    __syncthreads(); load_w64(sW, W3r, t); __syncthreads();
    tacc<64>(acc, xr, sW, tx, 1.0f);
    store_relu8<128>(g_xab + (size_t)row0 * 128 + 64 + tx * 8, row0, acc);
}

// t1 = relu( lamx*(x@WX) + laml*(aggLL@W2l + xl@W2r) + lamh*(aggHH@W4l + xh@W4r) )
__global__ __launch_bounds__(256) void k_gemm3(const int* __restrict__ ccm,
                                               const float* __restrict__ W2l,
                                               const float* __restrict__ W2r,
                                               const float* __restrict__ W4l,
                                               const float* __restrict__ W4r,
                                               const float* __restrict__ WX,
                                               const float* __restrict__ lam1,
                                               const float* __restrict__ lam2) {
    __shared__ float sW[4096];
    int t = threadIdx.x;
    int tx = t & 7, ty = t >> 3;
    int row0 = blockIdx.x * 256 + ty;

    float a0 = __ldg(&lam1[0]), a1 = __ldg(&lam1[1]);
    float m1 = fmaxf(a0, a1);
    float e0 = expf(a0 - m1), e1 = expf(a1 - m1);
    float inv1 = 1.0f / (e0 + e1);
    float lamxl = e0 * inv1, laml = e1 * inv1;
    float b0 = __ldg(&lam2[0]), b1 = __ldg(&lam2[1]);
    float m2 = fmaxf(b0, b1);
    float f0 = expf(b0 - m2), f1 = expf(b1 - m2);
    float inv2 = 1.0f / (f0 + f1);
    float lamxh = f0 * inv2, lamh = f1 * inv2;

    float s[8];
#pragma unroll
    for (int r = 0; r < 8; r++) {
        int row = row0 + 32 * r;
        int rr = row < NN ? row : NN - 1;
        s[r] = ccm[rr] ? lamxl : lamxh;
    }

    const float* xr    = g_xpad + (size_t)row0 * 64;
    const float* aggLL = g_aggB + (size_t)row0 * 128;
    const float* aggHH = aggLL + 64;
    const float* xlr   = g_xab + (size_t)row0 * 128;
    const float* xhr   = xlr + 64;

    u64 acc[8][4];
    acc_zero8(acc);

    load_w64(sW, WX, t); __syncthreads();
    tacc_s<64>(acc, xr, sW, tx, s);
    __syncthreads(); load_w64s(sW, W2l, t, laml); __syncthreads();
    tacc<128>(acc, aggLL, sW, tx, 1.0f);
    __syncthreads(); load_w64s(sW, W2r, t, laml); __syncthreads();
    tacc<128>(acc, xlr, sW, tx, 1.0f);
    __syncthreads(); load_w64s(sW, W4l, t, lamh); __syncthreads();
    tacc<128>(acc, aggHH, sW, tx, 1.0f);
    __syncthreads(); load_w64s(sW, W4r, t, lamh); __syncthreads();
    tacc<128>(acc, xhr, sW, tx, 1.0f);

    store_relu8<64>(g_t1 + (size_t)row0 * 64 + tx * 8, row0, acc);
}

// out = t1 @ lin_W + lin_b   (64 -> 40), tiled; cols padded to 64 (tx>=5 unstored)
__global__ __launch_bounds__(256) void k_out(const float* __restrict__ linW,
                                             const float* __restrict__ linb,
                                             float* __restrict__ out) {
    __shared__ float sW[4096];
    __shared__ float sB[64];
    int t = threadIdx.x;
    int tx = t & 7, ty = t >> 3;
    int row0 = blockIdx.x * 256 + ty;

    {
        float4* dst = (float4*)sW;
        float4 z; z.x = z.y = z.z = z.w = 0.f;
#pragma unroll
        for (int i = 0; i < 4; i++) dst[t + i * 256] = z;
        if (t < 64) sB[t] = (t < 40) ? linb[t] : 0.f;
    }
    __syncthreads();
    {
        const float4* src = (const float4*)linW;
#pragma unroll
        for (int i = 0; i < 3; i++) {
            int idx = t + i * 256;
            if (idx < 640) {
                float4 v = src[idx];
                int f = idx * 4;
                int k = f / 40, c = f % 40;
                *(float4*)(sW + k * 64 + c) = v;
            }
        }
    }
    __syncthreads();

    u64 acc[8][4];
#pragma unroll
    for (int r = 0; r < 8; r++)
#pragma unroll
        for (int j = 0; j < 4; j++) acc[r][j] = pk(sB[tx * 8 + 2 * j], sB[tx * 8 + 2 * j + 1]);

    const float* A = g_t1 + (size_t)row0 * 64;
    tacc<64>(acc, A, sW, tx, 1.0f);

    if (tx < 5) {
#pragma unroll
        for (int r = 0; r < 8; r++) {
            int row = row0 + 32 * r;
            if (row < NN) {
                float2 a = up2(acc[r][0]);
                float2 b = up2(acc[r][1]);
                float2 c = up2(acc[r][2]);
                float2 d = up2(acc[r][3]);
                float4 v0, v1;
                v0.x = a.x; v0.y = a.y; v0.z = b.x; v0.w = b.y;
                v1.x = c.x; v1.y = c.y; v1.z = d.x; v1.w = d.y;
                float4* o = (float4*)(out + (size_t)row * 40 + tx * 8);
                o[0] = v0; o[1] = v1;
            }
        }
    }
}

// ---------------- launch ----------------
extern "C" void kernel_launch(void* const* d_in, const int* in_sizes, int n_in,
                              void* d_out, int out_size) {
    (void)in_sizes; (void)n_in; (void)out_size;
    const float* x    = (const float*)d_in[0];
    const int*   ei   = (const int*)d_in[1];
    const int*   ccm  = (const int*)d_in[2];
    const float* W1l  = (const float*)d_in[3];
    const float* W1r  = (const float*)d_in[4];
    const float* W2l  = (const float*)d_in[5];
    const float* W2r  = (const float*)d_in[6];
    const float* W3l  = (const float*)d_in[7];
    const float* W3r  = (const float*)d_in[8];
    const float* W4l  = (const float*)d_in[9];
    const float* W4r  = (const float*)d_in[10];
    const float* WX   = (const float*)d_in[11];
    const float* lam1 = (const float*)d_in[12];
    const float* lam2 = (const float*)d_in[13];
    const float* linW = (const float*)d_in[14];
    const float* linb = (const float*)d_in[15];
    float* out = (float*)d_out;

    const int GB = (NP / 256);   // 391 tiled blocks

    k_pre      <<<NN * 16 / 256, 256>>>(x);            // 6250 blocks, exact
    k_count    <<<(EE + 255) / 256, 256>>>(ei, ccm);
    k_scan1    <<<NB_SCAN, 1024>>>();
    k_scan2    <<<1, 128>>>();
    k_final_csr<<<(NN + 255) / 256, 256>>>(ccm);
    k_scatter  <<<(EE + 255) / 256, 256>>>(ei);
    k_spmmA    <<<(NN * 32 + 255) / 256, 256>>>(x, ccm);
    k_gemmA    <<<GB, 256>>>(W1l, W1r, W3l, W3r);
    k_spmmB    <<<(NN * 32 + 255) / 256, 256>>>();
    k_gemm3    <<<GB, 256>>>(ccm, W2l, W2r, W4l, W4r, WX, lam1, lam2);
    k_out      <<<GB, 256>>>(linW, linb, out);
}